// round 12
// baseline (speedup 1.0000x reference)
#include <cuda_runtime.h>
#include <cuda_fp16.h>
#include <math.h>

#define N_NODES 100000
#define N_EDGES 1000000
#define N_GRAPHS 4096
#define F_IN 9
#define H 64
#define SCAN_BLK 1024
#define N_SBLK ((N_NODES + SCAN_BLK - 1) / SCAN_BLK)  // 98
#define N_PAD 100128                                   // >= 782*128

// ---------------- device scratch ----------------
__device__ int     g_is64;
__device__ int     g_deg[N_NODES];                 // degree incl. self loop
__device__ int     g_off[N_NODES];                 // CSR offsets (by dst)
__device__ int     g_cur[N_NODES];                 // fill cursor, INIT = g_off
__device__ float   g_dis[N_NODES];                 // rsqrt(deg)
__device__ int     g_bsum[N_SBLK];
__device__ int     g_csr[N_NODES + N_EDGES];
__device__ float   g_xp[(size_t)N_NODES * F_IN];   // dis[v] * x[v]  (fp32)
__device__ float   g_xa[(size_t)N_NODES * F_IN];   // aggregated input (fp32)
__device__ __half2 g_p16[(size_t)N_PAD * 32];      // p = dis*relu(...) (fp16)
__device__ __half2 g_t16[(size_t)N_PAD * 32];      // aggregated (fp16)
__device__ uint2   g_wpk[3][1024];                 // fragment-packed fp16 weights W2..W4
__device__ float   g_pool[(size_t)N_GRAPHS * H];
__device__ float   g_cnt[N_GRAPHS];

__device__ __forceinline__ long long load_idx(const void* p, long long i, int is64) {
    if (is64) return ((const long long*)p)[i];
    return (long long)((const int*)p)[i];
}

// ---------------- init (+ dtype detection in thread 0) ----------------
__global__ void k_init(const void* ei) {
    int i = blockIdx.x * blockDim.x + threadIdx.x;
    if (i == 0) {
        const int* p = (const int*)ei;
        int all0 = 1;
        #pragma unroll
        for (int k = 0; k < 32; k++)
            if (p[2 * k + 1] != 0) all0 = 0;
        g_is64 = all0;
    }
    if (i < N_NODES) g_deg[i] = 1;
    if (i < N_GRAPHS * H) g_pool[i] = 0.f;
    if (i < N_GRAPHS) g_cnt[i] = 0.f;
}

// ---------------- degree count ----------------
__global__ void k_count(const void* ei) {
    int i = blockIdx.x * blockDim.x + threadIdx.x;
    if (i >= N_EDGES) return;
    int d = (int)load_idx(ei, (long long)N_EDGES + i, g_is64);
    atomicAdd(&g_deg[d], 1);
}

// ---------------- multi-block scan (R6-proven 3-kernel version) ----------
__global__ void k_bsum() {
    int i = blockIdx.x * SCAN_BLK + threadIdx.x;
    int d = (i < N_NODES) ? g_deg[i] : 0;
    #pragma unroll
    for (int o = 16; o > 0; o >>= 1) d += __shfl_down_sync(0xffffffffu, d, o);
    __shared__ int ws[32];
    if ((threadIdx.x & 31) == 0) ws[threadIdx.x >> 5] = d;
    __syncthreads();
    if (threadIdx.x < 32) {
        int v = ws[threadIdx.x];
        #pragma unroll
        for (int o = 16; o > 0; o >>= 1) v += __shfl_down_sync(0xffffffffu, v, o);
        if (threadIdx.x == 0) g_bsum[blockIdx.x] = v;
    }
}

__global__ void k_bscan() {
    __shared__ int s[128];
    int t = threadIdx.x;
    int v = (t < N_SBLK) ? g_bsum[t] : 0;
    s[t] = v;
    __syncthreads();
    for (int d = 1; d < 128; d <<= 1) {
        int u = (t >= d) ? s[t - d] : 0;
        __syncthreads();
        s[t] += u;
        __syncthreads();
    }
    if (t < N_SBLK) g_bsum[t] = s[t] - v;
}

__global__ void k_off() {
    int i = blockIdx.x * SCAN_BLK + threadIdx.x;
    int d = (i < N_NODES) ? g_deg[i] : 0;
    int lane = threadIdx.x & 31, w = threadIdx.x >> 5;
    int inc = d;
    #pragma unroll
    for (int o = 1; o < 32; o <<= 1) {
        int u = __shfl_up_sync(0xffffffffu, inc, o);
        if (lane >= o) inc += u;
    }
    __shared__ int ws[32];
    if (lane == 31) ws[w] = inc;
    __syncthreads();
    if (w == 0) {
        int v = ws[lane];
        int inc2 = v;
        #pragma unroll
        for (int o = 1; o < 32; o <<= 1) {
            int u = __shfl_up_sync(0xffffffffu, inc2, o);
            if (lane >= o) inc2 += u;
        }
        ws[lane] = inc2 - v;
    }
    __syncthreads();
    if (i < N_NODES) {
        int off = g_bsum[blockIdx.x] + ws[w] + inc - d;
        g_off[i] = off;
        g_cur[i] = off;                      // cursor starts AT the offset
        g_dis[i] = rsqrtf((float)d);
    }
}

// ---------------- CSR fill: one less random load per edge ----------------
__global__ void k_fill(const void* ei) {
    int i = blockIdx.x * blockDim.x + threadIdx.x;
    if (i >= N_EDGES) return;
    int is64 = g_is64;
    int s = (int)load_idx(ei, i, is64);
    int d = (int)load_idx(ei, (long long)N_EDGES + i, is64);
    int pos = atomicAdd(&g_cur[d], 1);       // pos = off[d] + slot, directly
    g_csr[pos] = s;
}

// ---------------- xp = dis * x (coalesced) ----------------
__global__ void k_xp(const float* __restrict__ x) {
    int t = blockIdx.x * blockDim.x + threadIdx.x;
    if (t >= N_NODES * F_IN) return;
    int v = t / F_IN;
    g_xp[t] = g_dis[v] * x[t];
}

// ---------------- pack W2..W4 into mma B-fragment order ----------------
__global__ void k_packW(const float* __restrict__ W2, const float* __restrict__ W3,
                        const float* __restrict__ W4) {
    int id = blockIdx.x * 256 + threadIdx.x;
    if (id >= 3 * 1024) return;
    const float* W = (id < 1024) ? W2 : ((id < 2048) ? W3 : W4);
    int idx = id & 1023;
    int ks = idx >> 8, nt = (idx >> 5) & 7, l = idx & 31;
    int g = l >> 2, t = l & 3;
    int n = nt * 8 + g;
    int k0 = ks * 16 + 2 * t;
    __half2 b0 = __floats2half2_rn(W[k0 * 64 + n], W[(k0 + 1) * 64 + n]);
    __half2 b1 = __floats2half2_rn(W[(k0 + 8) * 64 + n], W[(k0 + 9) * 64 + n]);
    uint2 u;
    u.x = *reinterpret_cast<unsigned*>(&b0);
    u.y = *reinterpret_cast<unsigned*>(&b1);
    g_wpk[id >> 10][idx] = u;
}

// ---------------- layer-1 aggregation on xp (thread per (node,col)) ------
__global__ void k_agg9(const void* batch) {
    int t = blockIdx.x * blockDim.x + threadIdx.x;
    if (t >= N_NODES * F_IN) return;
    int v = t / F_IN;
    int c = t - v * F_IN;
    float acc = g_xp[(size_t)v * F_IN + c];
    int st = g_off[v];
    int cnt = g_deg[v] - 1;                  // real edges (deg incl. self loop)
    #pragma unroll 4
    for (int e = 0; e < cnt; e++) {
        int s = g_csr[st + e];
        acc += g_xp[(size_t)s * F_IN + c];
    }
    g_xa[(size_t)v * F_IN + c] = g_dis[v] * acc;
    if (c == 0) {
        int g = (int)load_idx(batch, v, g_is64);
        atomicAdd(&g_cnt[g], 1.f);
    }
}

// ---------------- layer-1 GEMM (K=9): p16 = dis*relu(xa @ W1 + b1) -------
__global__ void __launch_bounds__(256)
k_gemm9(const float* __restrict__ in, const float* __restrict__ W,
        const float* __restrict__ bias, __half2* __restrict__ out) {
    __shared__ float sHT[F_IN * 132];
    __shared__ float sW[F_IN * 64];
    int tid = threadIdx.x;
    int rblk = blockIdx.x * 128;
    for (int i = tid; i < F_IN * 64; i += 256) sW[i] = W[i];
    for (int i = tid; i < 128 * F_IN; i += 256) {
        int r = i / F_IN, k = i - r * F_IN;
        sHT[k * 132 + r] = (rblk + r < N_NODES) ? in[(size_t)(rblk + r) * F_IN + k] : 0.f;
    }
    __syncthreads();
    int cg = tid & 15, rg = tid >> 4;
    int c0 = cg * 4, r0 = rg * 8;
    float4 acc[8];
    #pragma unroll
    for (int j = 0; j < 8; j++) acc[j] = make_float4(0.f, 0.f, 0.f, 0.f);
    #pragma unroll
    for (int k = 0; k < F_IN; k++) {
        float4 w = *(const float4*)(sW + k * 64 + c0);
        float4 h0 = *(const float4*)(sHT + k * 132 + r0);
        float4 h1 = *(const float4*)(sHT + k * 132 + r0 + 4);
        float hv[8] = {h0.x, h0.y, h0.z, h0.w, h1.x, h1.y, h1.z, h1.w};
        #pragma unroll
        for (int j = 0; j < 8; j++) {
            acc[j].x = fmaf(hv[j], w.x, acc[j].x);
            acc[j].y = fmaf(hv[j], w.y, acc[j].y);
            acc[j].z = fmaf(hv[j], w.z, acc[j].z);
            acc[j].w = fmaf(hv[j], w.w, acc[j].w);
        }
    }
    float4 b = *(const float4*)(bias + c0);
    #pragma unroll
    for (int j = 0; j < 8; j++) {
        int row = rblk + r0 + j;
        if (row >= N_NODES) continue;
        float dv = g_dis[row];
        float ox = dv * fmaxf(acc[j].x + b.x, 0.f);
        float oy = dv * fmaxf(acc[j].y + b.y, 0.f);
        float oz = dv * fmaxf(acc[j].z + b.z, 0.f);
        float ow = dv * fmaxf(acc[j].w + b.w, 0.f);
        out[(size_t)row * 32 + cg * 2 + 0] = __floats2half2_rn(ox, oy);
        out[(size_t)row * 32 + cg * 2 + 1] = __floats2half2_rn(oz, ow);
    }
}

// ---------------- fp16 aggregation: warp per node (pure sum of p) --------
__global__ void k_agg64h(const __half2* __restrict__ pin, __half2* __restrict__ tout) {
    int warp = threadIdx.x >> 5;
    int lane = threadIdx.x & 31;
    int v = blockIdx.x * 4 + warp;
    if (v >= N_NODES) return;
    float2 sf = __half22float2(pin[(size_t)v * 32 + lane]);
    float a0 = sf.x;
    float a1 = sf.y;
    int st = g_off[v];
    int cnt = g_deg[v] - 1;
    for (int base = 0; base < cnt; base += 32) {
        int e = base + lane;
        int s = (e < cnt) ? g_csr[st + e] : 0;
        int m = min(32, cnt - base);
        #pragma unroll 4
        for (int j = 0; j < m; j++) {
            int sj = __shfl_sync(0xffffffffu, s, j);
            float2 vf = __half22float2(pin[(size_t)sj * 32 + lane]);
            a0 += vf.x;
            a1 += vf.y;
        }
    }
    float dv = g_dis[v];
    tout[(size_t)v * 32 + lane] = __floats2half2_rn(dv * a0, dv * a1);
}

// ---------------- tensor-core GEMM ----------------------------------------
// MODE 0: pout = dis*relu(A@W + b) (fp16). MODE 1: pool relu(A@W+b).
template <int MODE>
__global__ void __launch_bounds__(256)
k_hgemm(const unsigned* __restrict__ A, const uint2* __restrict__ Wpk,
        const float* __restrict__ bias, __half2* __restrict__ pout,
        const void* batch) {
    int w = threadIdx.x >> 5, l = threadIdx.x & 31;
    int g = l >> 2, t = l & 3;
    int row0 = blockIdx.x * 128 + w * 16;
    int ra = row0 + g, rb = row0 + g + 8;

    float acc[8][4];
    #pragma unroll
    for (int i = 0; i < 8; i++)
        acc[i][0] = acc[i][1] = acc[i][2] = acc[i][3] = 0.f;

    #pragma unroll
    for (int ks = 0; ks < 4; ks++) {
        unsigned a0 = A[(size_t)ra * 32 + ks * 8 + t];
        unsigned a1 = A[(size_t)rb * 32 + ks * 8 + t];
        unsigned a2 = A[(size_t)ra * 32 + ks * 8 + t + 4];
        unsigned a3 = A[(size_t)rb * 32 + ks * 8 + t + 4];
        #pragma unroll
        for (int nt = 0; nt < 8; nt++) {
            uint2 b = Wpk[(ks * 8 + nt) * 32 + l];
            asm volatile(
                "mma.sync.aligned.m16n8k16.row.col.f32.f16.f16.f32 "
                "{%0,%1,%2,%3}, {%4,%5,%6,%7}, {%8,%9}, {%0,%1,%2,%3};"
                : "+f"(acc[nt][0]), "+f"(acc[nt][1]),
                  "+f"(acc[nt][2]), "+f"(acc[nt][3])
                : "r"(a0), "r"(a1), "r"(a2), "r"(a3), "r"(b.x), "r"(b.y));
        }
    }

    if (MODE == 0) {
        float da = (ra < N_NODES) ? g_dis[ra] : 0.f;
        float db = (rb < N_NODES) ? g_dis[rb] : 0.f;
        #pragma unroll
        for (int nt = 0; nt < 8; nt++) {
            float2 bv = ((const float2*)bias)[nt * 4 + t];
            float o0 = da * fmaxf(acc[nt][0] + bv.x, 0.f);
            float o1 = da * fmaxf(acc[nt][1] + bv.y, 0.f);
            float o2 = db * fmaxf(acc[nt][2] + bv.x, 0.f);
            float o3 = db * fmaxf(acc[nt][3] + bv.y, 0.f);
            pout[(size_t)ra * 32 + nt * 4 + t] = __floats2half2_rn(o0, o1);
            pout[(size_t)rb * 32 + nt * 4 + t] = __floats2half2_rn(o2, o3);
        }
    } else {
        int is64 = g_is64;
        int ga = (ra < N_NODES) ? (int)load_idx(batch, ra, is64) : 0;
        int gb = (rb < N_NODES) ? (int)load_idx(batch, rb, is64) : 0;
        #pragma unroll
        for (int nt = 0; nt < 8; nt++) {
            float2 bv = ((const float2*)bias)[nt * 4 + t];
            float o0 = fmaxf(acc[nt][0] + bv.x, 0.f);
            float o1 = fmaxf(acc[nt][1] + bv.y, 0.f);
            float o2 = fmaxf(acc[nt][2] + bv.x, 0.f);
            float o3 = fmaxf(acc[nt][3] + bv.y, 0.f);
            if (ra < N_NODES) {
                atomicAdd(&g_pool[(size_t)ga * 64 + nt * 8 + 2 * t + 0], o0);
                atomicAdd(&g_pool[(size_t)ga * 64 + nt * 8 + 2 * t + 1], o1);
            }
            if (rb < N_NODES) {
                atomicAdd(&g_pool[(size_t)gb * 64 + nt * 8 + 2 * t + 0], o2);
                atomicAdd(&g_pool[(size_t)gb * 64 + nt * 8 + 2 * t + 1], o3);
            }
        }
    }
}

// ---------------- final: mean + linear head ----------------
__global__ void k_final(const float* __restrict__ Wout, const float* __restrict__ bout,
                        float* __restrict__ out) {
    int warp = threadIdx.x >> 5;
    int lane = threadIdx.x & 31;
    int g = blockIdx.x * 4 + warp;
    if (g >= N_GRAPHS) return;
    float inv = 1.f / fmaxf(g_cnt[g], 1.f);
    float s = g_pool[(size_t)g * 64 + lane] * Wout[lane] +
              g_pool[(size_t)g * 64 + lane + 32] * Wout[lane + 32];
    #pragma unroll
    for (int o = 16; o > 0; o >>= 1) s += __shfl_down_sync(0xffffffffu, s, o);
    if (lane == 0) out[g] = s * inv + bout[0];
}

// ---------------- launch ----------------
extern "C" void kernel_launch(void* const* d_in, const int* in_sizes, int n_in,
                              void* d_out, int out_size) {
    const float* x     = (const float*)d_in[0];
    const void*  ei    = d_in[1];
    const void*  batch = d_in[2];
    const float* W1 = (const float*)d_in[3];
    const float* b1 = (const float*)d_in[4];
    const float* W2 = (const float*)d_in[5];
    const float* b2 = (const float*)d_in[6];
    const float* W3 = (const float*)d_in[7];
    const float* b3 = (const float*)d_in[8];
    const float* W4 = (const float*)d_in[9];
    const float* b4 = (const float*)d_in[10];
    const float* Wout = (const float*)d_in[11];
    const float* bout = (const float*)d_in[12];
    float* out = (float*)d_out;

    float*   xa;  cudaGetSymbolAddress((void**)&xa, g_xa);
    __half2* p16; cudaGetSymbolAddress((void**)&p16, g_p16);
    __half2* t16; cudaGetSymbolAddress((void**)&t16, g_t16);
    uint2*   wpk; cudaGetSymbolAddress((void**)&wpk, g_wpk);

    int init_n = (N_GRAPHS * H > N_NODES) ? N_GRAPHS * H : N_NODES;
    k_init<<<(init_n + 255) / 256, 256>>>(ei);

    k_count<<<(N_EDGES + 255) / 256, 256>>>(ei);
    k_bsum<<<N_SBLK, SCAN_BLK>>>();
    k_bscan<<<1, 128>>>();
    k_off<<<N_SBLK, SCAN_BLK>>>();
    k_fill<<<(N_EDGES + 255) / 256, 256>>>(ei);
    k_xp<<<(N_NODES * F_IN + 255) / 256, 256>>>(x);
    k_packW<<<12, 256>>>(W2, W3, W4);

    const int agg_blocks  = (N_NODES + 3) / 4;
    const int gemm_blocks = (N_NODES + 127) / 128;

    // layer 1
    k_agg9<<<(N_NODES * F_IN + 255) / 256, 256>>>(batch);
    k_gemm9<<<gemm_blocks, 256>>>(xa, W1, b1, p16);
    // layer 2
    k_agg64h<<<agg_blocks, 128>>>(p16, t16);
    k_hgemm<0><<<gemm_blocks, 256>>>((const unsigned*)t16, wpk + 0 * 1024, b2, p16, batch);
    // layer 3
    k_agg64h<<<agg_blocks, 128>>>(p16, t16);
    k_hgemm<0><<<gemm_blocks, 256>>>((const unsigned*)t16, wpk + 1 * 1024, b3, p16, batch);
    // layer 4: GEMM epilogue pools directly
    k_agg64h<<<agg_blocks, 128>>>(p16, t16);
    k_hgemm<1><<<gemm_blocks, 256>>>((const unsigned*)t16, wpk + 2 * 1024, b4, nullptr, batch);

    k_final<<<(N_GRAPHS + 3) / 4, 128>>>(Wout, bout, out);
}

// round 13
// speedup vs baseline: 1.0368x; 1.0368x over previous
#include <cuda_runtime.h>
#include <cuda_fp16.h>
#include <math.h>

#define N_NODES 100000
#define N_EDGES 1000000
#define N_GRAPHS 4096
#define F_IN 9
#define H 64
#define SCAN_BLK 1024
#define N_SBLK ((N_NODES + SCAN_BLK - 1) / SCAN_BLK)  // 98
#define N_PAD 100128                                   // >= 782*128

// ---------------- device scratch ----------------
__device__ int     g_is64;
__device__ int     g_deg[N_NODES];                 // degree incl. self loop
__device__ int     g_off[N_NODES];
__device__ int     g_cur[N_NODES];                 // fill cursor = #real edges
__device__ float   g_dis[N_NODES];                 // rsqrt(deg)
__device__ int     g_bsum[N_SBLK];
__device__ int     g_csr[N_NODES + N_EDGES];
__device__ float   g_xp[(size_t)N_NODES * F_IN];   // dis[v] * x[v]  (fp32)
__device__ float   g_xa[(size_t)N_NODES * F_IN];   // aggregated input (fp32)
__device__ __half2 g_p16[(size_t)N_PAD * 32];      // p = dis*relu(...) (fp16)
__device__ __half2 g_t16[(size_t)N_PAD * 32];      // aggregated (fp16)
__device__ uint2   g_wpk[3][1024];                 // fragment-packed fp16 weights W2..W4
__device__ float   g_pool[(size_t)N_GRAPHS * H];
__device__ float   g_cnt[N_GRAPHS];

__device__ __forceinline__ long long load_idx(const void* p, long long i, int is64) {
    if (is64) return ((const long long*)p)[i];
    return (long long)((const int*)p)[i];
}

// ---------------- init (+ dtype detection in thread 0) ----------------
__global__ void k_init(const void* ei) {
    cudaGridDependencySynchronize();
    int i = blockIdx.x * blockDim.x + threadIdx.x;
    if (i == 0) {
        const int* p = (const int*)ei;
        int all0 = 1;
        #pragma unroll
        for (int k = 0; k < 32; k++)
            if (p[2 * k + 1] != 0) all0 = 0;
        g_is64 = all0;
    }
    if (i < N_NODES) { g_deg[i] = 1; g_cur[i] = 0; }
    if (i < N_GRAPHS * H) g_pool[i] = 0.f;
    if (i < N_GRAPHS) g_cnt[i] = 0.f;
}

// ---------------- degree count ----------------
__global__ void k_count(const void* ei) {
    cudaGridDependencySynchronize();
    int i = blockIdx.x * blockDim.x + threadIdx.x;
    if (i >= N_EDGES) return;
    int d = (int)load_idx(ei, (long long)N_EDGES + i, g_is64);
    atomicAdd(&g_deg[d], 1);
}

// ---------------- multi-block scan ----------------
__global__ void k_bsum() {
    cudaGridDependencySynchronize();
    int i = blockIdx.x * SCAN_BLK + threadIdx.x;
    int d = (i < N_NODES) ? g_deg[i] : 0;
    #pragma unroll
    for (int o = 16; o > 0; o >>= 1) d += __shfl_down_sync(0xffffffffu, d, o);
    __shared__ int ws[32];
    if ((threadIdx.x & 31) == 0) ws[threadIdx.x >> 5] = d;
    __syncthreads();
    if (threadIdx.x < 32) {
        int v = ws[threadIdx.x];
        #pragma unroll
        for (int o = 16; o > 0; o >>= 1) v += __shfl_down_sync(0xffffffffu, v, o);
        if (threadIdx.x == 0) g_bsum[blockIdx.x] = v;
    }
}

__global__ void k_bscan() {
    cudaGridDependencySynchronize();
    __shared__ int s[128];
    int t = threadIdx.x;
    int v = (t < N_SBLK) ? g_bsum[t] : 0;
    s[t] = v;
    __syncthreads();
    for (int d = 1; d < 128; d <<= 1) {
        int u = (t >= d) ? s[t - d] : 0;
        __syncthreads();
        s[t] += u;
        __syncthreads();
    }
    if (t < N_SBLK) g_bsum[t] = s[t] - v;
}

__global__ void k_off() {
    cudaGridDependencySynchronize();
    int i = blockIdx.x * SCAN_BLK + threadIdx.x;
    int d = (i < N_NODES) ? g_deg[i] : 0;
    int lane = threadIdx.x & 31, w = threadIdx.x >> 5;
    int inc = d;
    #pragma unroll
    for (int o = 1; o < 32; o <<= 1) {
        int u = __shfl_up_sync(0xffffffffu, inc, o);
        if (lane >= o) inc += u;
    }
    __shared__ int ws[32];
    if (lane == 31) ws[w] = inc;
    __syncthreads();
    if (w == 0) {
        int v = ws[lane];
        int inc2 = v;
        #pragma unroll
        for (int o = 1; o < 32; o <<= 1) {
            int u = __shfl_up_sync(0xffffffffu, inc2, o);
            if (lane >= o) inc2 += u;
        }
        ws[lane] = inc2 - v;
    }
    __syncthreads();
    if (i < N_NODES) {
        g_off[i] = g_bsum[blockIdx.x] + ws[w] + inc - d;
        g_dis[i] = rsqrtf((float)d);
    }
}

// ---------------- CSR fill ----------------
__global__ void k_fill(const void* ei) {
    cudaGridDependencySynchronize();
    int i = blockIdx.x * blockDim.x + threadIdx.x;
    if (i >= N_EDGES) return;
    int is64 = g_is64;
    int s = (int)load_idx(ei, i, is64);
    int d = (int)load_idx(ei, (long long)N_EDGES + i, is64);
    int p = atomicAdd(&g_cur[d], 1);
    g_csr[g_off[d] + p] = s;
}

// ---------------- xp = dis * x (coalesced) ----------------
__global__ void k_xp(const float* __restrict__ x) {
    cudaGridDependencySynchronize();
    int t = blockIdx.x * blockDim.x + threadIdx.x;
    if (t >= N_NODES * F_IN) return;
    int v = t / F_IN;
    g_xp[t] = g_dis[v] * x[t];
}

// ---------------- pack W2..W4 into mma B-fragment order ----------------
__global__ void k_packW(const float* __restrict__ W2, const float* __restrict__ W3,
                        const float* __restrict__ W4) {
    cudaGridDependencySynchronize();
    int id = blockIdx.x * 256 + threadIdx.x;
    if (id >= 3 * 1024) return;
    const float* W = (id < 1024) ? W2 : ((id < 2048) ? W3 : W4);
    int idx = id & 1023;
    int ks = idx >> 8, nt = (idx >> 5) & 7, l = idx & 31;
    int g = l >> 2, t = l & 3;
    int n = nt * 8 + g;
    int k0 = ks * 16 + 2 * t;
    __half2 b0 = __floats2half2_rn(W[k0 * 64 + n], W[(k0 + 1) * 64 + n]);
    __half2 b1 = __floats2half2_rn(W[(k0 + 8) * 64 + n], W[(k0 + 9) * 64 + n]);
    uint2 u;
    u.x = *reinterpret_cast<unsigned*>(&b0);
    u.y = *reinterpret_cast<unsigned*>(&b1);
    g_wpk[id >> 10][idx] = u;
}

// ---------------- layer-1 aggregation on xp ----------------
__global__ void k_agg9(const void* batch) {
    cudaGridDependencySynchronize();
    int t = blockIdx.x * blockDim.x + threadIdx.x;
    if (t >= N_NODES * F_IN) return;
    int v = t / F_IN;
    int c = t - v * F_IN;
    float acc = g_xp[(size_t)v * F_IN + c];
    int st = g_off[v];
    int cnt = g_cur[v];
    #pragma unroll 4
    for (int e = 0; e < cnt; e++) {
        int s = g_csr[st + e];
        acc += g_xp[(size_t)s * F_IN + c];
    }
    g_xa[(size_t)v * F_IN + c] = g_dis[v] * acc;
    if (c == 0) {
        int g = (int)load_idx(batch, v, g_is64);
        atomicAdd(&g_cnt[g], 1.f);
    }
}

// ---------------- layer-1 GEMM (K=9): p16 = dis*relu(xa @ W1 + b1) -------
__global__ void __launch_bounds__(256)
k_gemm9(const float* __restrict__ in, const float* __restrict__ W,
        const float* __restrict__ bias, __half2* __restrict__ out) {
    cudaGridDependencySynchronize();
    __shared__ float sHT[F_IN * 132];
    __shared__ float sW[F_IN * 64];
    int tid = threadIdx.x;
    int rblk = blockIdx.x * 128;
    for (int i = tid; i < F_IN * 64; i += 256) sW[i] = W[i];
    for (int i = tid; i < 128 * F_IN; i += 256) {
        int r = i / F_IN, k = i - r * F_IN;
        sHT[k * 132 + r] = (rblk + r < N_NODES) ? in[(size_t)(rblk + r) * F_IN + k] : 0.f;
    }
    __syncthreads();
    int cg = tid & 15, rg = tid >> 4;
    int c0 = cg * 4, r0 = rg * 8;
    float4 acc[8];
    #pragma unroll
    for (int j = 0; j < 8; j++) acc[j] = make_float4(0.f, 0.f, 0.f, 0.f);
    #pragma unroll
    for (int k = 0; k < F_IN; k++) {
        float4 w = *(const float4*)(sW + k * 64 + c0);
        float4 h0 = *(const float4*)(sHT + k * 132 + r0);
        float4 h1 = *(const float4*)(sHT + k * 132 + r0 + 4);
        float hv[8] = {h0.x, h0.y, h0.z, h0.w, h1.x, h1.y, h1.z, h1.w};
        #pragma unroll
        for (int j = 0; j < 8; j++) {
            acc[j].x = fmaf(hv[j], w.x, acc[j].x);
            acc[j].y = fmaf(hv[j], w.y, acc[j].y);
            acc[j].z = fmaf(hv[j], w.z, acc[j].z);
            acc[j].w = fmaf(hv[j], w.w, acc[j].w);
        }
    }
    float4 b = *(const float4*)(bias + c0);
    #pragma unroll
    for (int j = 0; j < 8; j++) {
        int row = rblk + r0 + j;
        if (row >= N_NODES) continue;
        float dv = g_dis[row];
        float ox = dv * fmaxf(acc[j].x + b.x, 0.f);
        float oy = dv * fmaxf(acc[j].y + b.y, 0.f);
        float oz = dv * fmaxf(acc[j].z + b.z, 0.f);
        float ow = dv * fmaxf(acc[j].w + b.w, 0.f);
        out[(size_t)row * 32 + cg * 2 + 0] = __floats2half2_rn(ox, oy);
        out[(size_t)row * 32 + cg * 2 + 1] = __floats2half2_rn(oz, ow);
    }
}

// ---------------- fp16 aggregation: warp per node (pure sum of p) --------
__global__ void k_agg64h(const __half2* __restrict__ pin, __half2* __restrict__ tout) {
    cudaGridDependencySynchronize();
    int warp = threadIdx.x >> 5;
    int lane = threadIdx.x & 31;
    int v = blockIdx.x * 4 + warp;
    if (v >= N_NODES) return;
    float2 sf = __half22float2(pin[(size_t)v * 32 + lane]);
    float a0 = sf.x;
    float a1 = sf.y;
    int st = g_off[v];
    int cnt = g_cur[v];
    for (int base = 0; base < cnt; base += 32) {
        int e = base + lane;
        int s = (e < cnt) ? g_csr[st + e] : 0;
        int m = min(32, cnt - base);
        #pragma unroll 4
        for (int j = 0; j < m; j++) {
            int sj = __shfl_sync(0xffffffffu, s, j);
            float2 vf = __half22float2(pin[(size_t)sj * 32 + lane]);
            a0 += vf.x;
            a1 += vf.y;
        }
    }
    float dv = g_dis[v];
    tout[(size_t)v * 32 + lane] = __floats2half2_rn(dv * a0, dv * a1);
}

// ---------------- tensor-core GEMM ----------------------------------------
// MODE 0: pout = dis*relu(A@W + b) (fp16). MODE 1: pool relu(A@W+b).
template <int MODE>
__global__ void __launch_bounds__(256)
k_hgemm(const unsigned* __restrict__ A, const uint2* __restrict__ Wpk,
        const float* __restrict__ bias, __half2* __restrict__ pout,
        const void* batch) {
    cudaGridDependencySynchronize();
    int w = threadIdx.x >> 5, l = threadIdx.x & 31;
    int g = l >> 2, t = l & 3;
    int row0 = blockIdx.x * 128 + w * 16;
    int ra = row0 + g, rb = row0 + g + 8;

    float acc[8][4];
    #pragma unroll
    for (int i = 0; i < 8; i++)
        acc[i][0] = acc[i][1] = acc[i][2] = acc[i][3] = 0.f;

    #pragma unroll
    for (int ks = 0; ks < 4; ks++) {
        unsigned a0 = A[(size_t)ra * 32 + ks * 8 + t];
        unsigned a1 = A[(size_t)rb * 32 + ks * 8 + t];
        unsigned a2 = A[(size_t)ra * 32 + ks * 8 + t + 4];
        unsigned a3 = A[(size_t)rb * 32 + ks * 8 + t + 4];
        #pragma unroll
        for (int nt = 0; nt < 8; nt++) {
            uint2 b = Wpk[(ks * 8 + nt) * 32 + l];
            asm volatile(
                "mma.sync.aligned.m16n8k16.row.col.f32.f16.f16.f32 "
                "{%0,%1,%2,%3}, {%4,%5,%6,%7}, {%8,%9}, {%0,%1,%2,%3};"
                : "+f"(acc[nt][0]), "+f"(acc[nt][1]),
                  "+f"(acc[nt][2]), "+f"(acc[nt][3])
                : "r"(a0), "r"(a1), "r"(a2), "r"(a3), "r"(b.x), "r"(b.y));
        }
    }

    if (MODE == 0) {
        float da = (ra < N_NODES) ? g_dis[ra] : 0.f;
        float db = (rb < N_NODES) ? g_dis[rb] : 0.f;
        #pragma unroll
        for (int nt = 0; nt < 8; nt++) {
            float2 bv = ((const float2*)bias)[nt * 4 + t];
            float o0 = da * fmaxf(acc[nt][0] + bv.x, 0.f);
            float o1 = da * fmaxf(acc[nt][1] + bv.y, 0.f);
            float o2 = db * fmaxf(acc[nt][2] + bv.x, 0.f);
            float o3 = db * fmaxf(acc[nt][3] + bv.y, 0.f);
            pout[(size_t)ra * 32 + nt * 4 + t] = __floats2half2_rn(o0, o1);
            pout[(size_t)rb * 32 + nt * 4 + t] = __floats2half2_rn(o2, o3);
        }
    } else {
        int is64 = g_is64;
        int ga = (ra < N_NODES) ? (int)load_idx(batch, ra, is64) : 0;
        int gb = (rb < N_NODES) ? (int)load_idx(batch, rb, is64) : 0;
        #pragma unroll
        for (int nt = 0; nt < 8; nt++) {
            float2 bv = ((const float2*)bias)[nt * 4 + t];
            float o0 = fmaxf(acc[nt][0] + bv.x, 0.f);
            float o1 = fmaxf(acc[nt][1] + bv.y, 0.f);
            float o2 = fmaxf(acc[nt][2] + bv.x, 0.f);
            float o3 = fmaxf(acc[nt][3] + bv.y, 0.f);
            if (ra < N_NODES) {
                atomicAdd(&g_pool[(size_t)ga * 64 + nt * 8 + 2 * t + 0], o0);
                atomicAdd(&g_pool[(size_t)ga * 64 + nt * 8 + 2 * t + 1], o1);
            }
            if (rb < N_NODES) {
                atomicAdd(&g_pool[(size_t)gb * 64 + nt * 8 + 2 * t + 0], o2);
                atomicAdd(&g_pool[(size_t)gb * 64 + nt * 8 + 2 * t + 1], o3);
            }
        }
    }
}

// ---------------- final: mean + linear head ----------------
__global__ void k_final(const float* __restrict__ Wout, const float* __restrict__ bout,
                        float* __restrict__ out) {
    cudaGridDependencySynchronize();
    int warp = threadIdx.x >> 5;
    int lane = threadIdx.x & 31;
    int g = blockIdx.x * 4 + warp;
    if (g >= N_GRAPHS) return;
    float inv = 1.f / fmaxf(g_cnt[g], 1.f);
    float s = g_pool[(size_t)g * 64 + lane] * Wout[lane] +
              g_pool[(size_t)g * 64 + lane + 32] * Wout[lane + 32];
    #pragma unroll
    for (int o = 16; o > 0; o >>= 1) s += __shfl_down_sync(0xffffffffu, s, o);
    if (lane == 0) out[g] = s * inv + bout[0];
}

// ---------------- PDL launch helper ----------------
template <typename F, typename... Args>
static inline void launch_pdl(F* kern, int grid, int block, Args... args) {
    cudaLaunchConfig_t cfg = {};
    cfg.gridDim = dim3(grid, 1, 1);
    cfg.blockDim = dim3(block, 1, 1);
    cfg.dynamicSmemBytes = 0;
    cfg.stream = 0;  // legacy default stream (same as <<<>>>)
    cudaLaunchAttribute attr[1];
    attr[0].id = cudaLaunchAttributeProgrammaticStreamSerialization;
    attr[0].val.programmaticStreamSerializationAllowed = 1;
    cfg.attrs = attr;
    cfg.numAttrs = 1;
    cudaLaunchKernelEx(&cfg, kern, args...);
}

// ---------------- launch ----------------
extern "C" void kernel_launch(void* const* d_in, const int* in_sizes, int n_in,
                              void* d_out, int out_size) {
    const float* x     = (const float*)d_in[0];
    const void*  ei    = d_in[1];
    const void*  batch = d_in[2];
    const float* W1 = (const float*)d_in[3];
    const float* b1 = (const float*)d_in[4];
    const float* W2 = (const float*)d_in[5];
    const float* b2 = (const float*)d_in[6];
    const float* W3 = (const float*)d_in[7];
    const float* b3 = (const float*)d_in[8];
    const float* W4 = (const float*)d_in[9];
    const float* b4 = (const float*)d_in[10];
    const float* Wout = (const float*)d_in[11];
    const float* bout = (const float*)d_in[12];
    float* out = (float*)d_out;

    float*   xa;  cudaGetSymbolAddress((void**)&xa, g_xa);
    __half2* p16; cudaGetSymbolAddress((void**)&p16, g_p16);
    __half2* t16; cudaGetSymbolAddress((void**)&t16, g_t16);
    uint2*   wpk; cudaGetSymbolAddress((void**)&wpk, g_wpk);

    int init_n = (N_GRAPHS * H > N_NODES) ? N_GRAPHS * H : N_NODES;
    launch_pdl(k_init, (init_n + 255) / 256, 256, ei);

    launch_pdl(k_count, (N_EDGES + 255) / 256, 256, ei);
    launch_pdl(k_bsum, N_SBLK, SCAN_BLK);
    launch_pdl(k_bscan, 1, 128);
    launch_pdl(k_off, N_SBLK, SCAN_BLK);
    launch_pdl(k_fill, (N_EDGES + 255) / 256, 256, ei);
    launch_pdl(k_xp, (N_NODES * F_IN + 255) / 256, 256, x);
    launch_pdl(k_packW, 12, 256, W2, W3, W4);

    const int agg_blocks  = (N_NODES + 3) / 4;
    const int gemm_blocks = (N_NODES + 127) / 128;

    // layer 1
    launch_pdl(k_agg9, (N_NODES * F_IN + 255) / 256, 256, batch);
    launch_pdl(k_gemm9, gemm_blocks, 256, xa, W1, b1, p16);
    // layer 2
    launch_pdl(k_agg64h, agg_blocks, 128, (const __half2*)p16, t16);
    launch_pdl(k_hgemm<0>, gemm_blocks, 256,
               (const unsigned*)t16, (const uint2*)(wpk + 0 * 1024), b2, p16, batch);
    // layer 3
    launch_pdl(k_agg64h, agg_blocks, 128, (const __half2*)p16, t16);
    launch_pdl(k_hgemm<0>, gemm_blocks, 256,
               (const unsigned*)t16, (const uint2*)(wpk + 1 * 1024), b3, p16, batch);
    // layer 4: GEMM epilogue pools directly
    launch_pdl(k_agg64h, agg_blocks, 128, (const __half2*)p16, t16);
    launch_pdl(k_hgemm<1>, gemm_blocks, 256,
               (const unsigned*)t16, (const uint2*)(wpk + 2 * 1024), b4, (__half2*)nullptr, batch);

    launch_pdl(k_final, (N_GRAPHS + 3) / 4, 128, Wout, bout, out);
}